// round 1
// baseline (speedup 1.0000x reference)
#include <cuda_runtime.h>
#include <cstdint>

// ---------------------------------------------------------------------------
// Problem constants
// ---------------------------------------------------------------------------
#define FH 128        // lr feature height
#define FW 128        // lr feature width
#define NPIX (FH*FW)  // 16384
#define QN 65536      // number of queries (256*256)
#define SN (4*QN)     // 262144 corner samples
#define K1 585        // 65*9 unfold dims
#define K1P 592       // padded to multiple of 16
#define NH 256        // hidden width

// ---------------------------------------------------------------------------
// Scratch (static device globals; no runtime allocation allowed)
// ---------------------------------------------------------------------------
__device__ float g_X[NPIX * K1P];      // im2col, 38.8 MB
__device__ float g_W0p[K1P * NH];      // padded W0 (conv part only)
__device__ float g_hp[NPIX * NH];      // per-pixel precomputed layer-0 (incl. b0)
__device__ float g_bufA[(size_t)SN * NH];  // 256 MiB
__device__ float g_bufB[(size_t)SN * NH];  // 256 MiB
__device__ float g_pred[SN * 3];

// ---------------------------------------------------------------------------
// Packed f32x2 helpers (sm_103a FFMA2)
// ---------------------------------------------------------------------------
__device__ __forceinline__ unsigned long long pk2(float lo, float hi) {
    unsigned long long r;
    asm("mov.b64 %0, {%1, %2};" : "=l"(r) : "f"(lo), "f"(hi));
    return r;
}
__device__ __forceinline__ void upk2(unsigned long long v, float& lo, float& hi) {
    asm("mov.b64 {%0, %1}, %2;" : "=f"(lo), "=f"(hi) : "l"(v));
}
__device__ __forceinline__ unsigned long long fma2(unsigned long long a,
                                                   unsigned long long b,
                                                   unsigned long long c) {
    unsigned long long d;
    asm("fma.rn.f32x2 %0, %1, %2, %3;" : "=l"(d) : "l"(a), "l"(b), "l"(c));
    return d;
}

// ---------------------------------------------------------------------------
// Kernel 1: im2col of concat(masked_feat, mask) with 3x3 unfold, zero pad.
// X[p, t], t = c*9 + ki*3 + kj ; columns 585..591 zero.
// ---------------------------------------------------------------------------
__global__ void build_X(const float* __restrict__ mf, const float* __restrict__ mask) {
    int p = blockIdx.x;
    int t = threadIdx.x;
    int y = p >> 7, x = p & 127;
    float v = 0.f;
    if (t < K1) {
        int c = t / 9, r = t - c * 9;
        int ki = r / 3, kj = r - ki * 3;
        int yy = y + ki - 1, xx = x + kj - 1;
        if (yy >= 0 && yy < FH && xx >= 0 && xx < FW) {
            v = (c < 64) ? mf[(c << 14) + (yy << 7) + xx] : mask[(yy << 7) + xx];
        }
    }
    g_X[p * K1P + t] = v;
}

// ---------------------------------------------------------------------------
// Kernel 2: pad W0 conv rows into [K1P, NH] (rows 585.. zero; rel rows excluded)
// ---------------------------------------------------------------------------
__global__ void pad_W0(const float* __restrict__ W0) {
    int i = blockIdx.x * blockDim.x + threadIdx.x;
    if (i >= K1P * NH) return;
    int row = i / NH;
    g_W0p[i] = (row < K1) ? W0[i] : 0.f;   // i == row*NH + col, same layout
}

// ---------------------------------------------------------------------------
// SGEMM: C[M,N] = A[M,K] @ B[K,N] + bias, optional ReLU.
// Requirements: M % 128 == 0, N % 128 == 0, K % 16 == 0.
// 128x128 block tile, BK=16, 256 threads, 8x8 per-thread tile, FFMA2 inner.
// ---------------------------------------------------------------------------
#define BM 128
#define BN 128
#define BK 16

__global__ __launch_bounds__(256) void sgemm(const float* __restrict__ A,
                                             const float* __restrict__ B,
                                             const float* __restrict__ bias,
                                             float* __restrict__ C,
                                             int M, int K, int N, int relu) {
    __shared__ float As[BK][BM];
    __shared__ float Bs[BK][BN];

    const int tid = threadIdx.x;
    const int tx = tid & 15;    // n-dir
    const int ty = tid >> 4;    // m-dir
    const int bm = blockIdx.y * BM;
    const int bn = blockIdx.x * BN;

    unsigned long long acc[4][8];
#pragma unroll
    for (int i = 0; i < 4; i++)
#pragma unroll
        for (int j = 0; j < 8; j++) acc[i][j] = 0ULL;

    for (int k0 = 0; k0 < K; k0 += BK) {
        // Load A tile (transposed into As[k][m])
#pragma unroll
        for (int i = 0; i < 2; i++) {
            int li = tid + i * 256;           // 0..511
            int m = li >> 2;                  // 0..127
            int k4 = (li & 3) << 2;           // 0,4,8,12
            float4 v = *reinterpret_cast<const float4*>(&A[(size_t)(bm + m) * K + k0 + k4]);
            As[k4 + 0][m] = v.x;
            As[k4 + 1][m] = v.y;
            As[k4 + 2][m] = v.z;
            As[k4 + 3][m] = v.w;
        }
        // Load B tile (Bs[k][n])
#pragma unroll
        for (int i = 0; i < 2; i++) {
            int li = tid + i * 256;
            int k = li >> 5;                  // 0..15
            int n4 = (li & 31) << 2;          // 0..124
            *reinterpret_cast<float4*>(&Bs[k][n4]) =
                *reinterpret_cast<const float4*>(&B[(size_t)(k0 + k) * N + bn + n4]);
        }
        __syncthreads();

#pragma unroll
        for (int kk = 0; kk < BK; kk++) {
            const ulonglong2* ap = reinterpret_cast<const ulonglong2*>(&As[kk][ty * 8]);
            ulonglong2 a01 = ap[0];   // rows (0,1),(2,3)
            ulonglong2 a23 = ap[1];   // rows (4,5),(6,7)
            float4 b0v = *reinterpret_cast<const float4*>(&Bs[kk][tx * 8]);
            float4 b1v = *reinterpret_cast<const float4*>(&Bs[kk][tx * 8 + 4]);
            float bv[8] = {b0v.x, b0v.y, b0v.z, b0v.w, b1v.x, b1v.y, b1v.z, b1v.w};
#pragma unroll
            for (int j = 0; j < 8; j++) {
                unsigned long long bb = pk2(bv[j], bv[j]);
                acc[0][j] = fma2(a01.x, bb, acc[0][j]);
                acc[1][j] = fma2(a01.y, bb, acc[1][j]);
                acc[2][j] = fma2(a23.x, bb, acc[2][j]);
                acc[3][j] = fma2(a23.y, bb, acc[3][j]);
            }
        }
        __syncthreads();
    }

    // Epilogue
    float cv[8][8];
#pragma unroll
    for (int p = 0; p < 4; p++)
#pragma unroll
        for (int j = 0; j < 8; j++) upk2(acc[p][j], cv[2 * p][j], cv[2 * p + 1][j]);

    float bload[8];
#pragma unroll
    for (int j = 0; j < 8; j++) bload[j] = bias[bn + tx * 8 + j];

#pragma unroll
    for (int r = 0; r < 8; r++) {
        int m = bm + ty * 8 + r;
        float o[8];
#pragma unroll
        for (int j = 0; j < 8; j++) {
            float v = cv[r][j] + bload[j];
            o[j] = relu ? fmaxf(v, 0.f) : v;
        }
        float* cp = &C[(size_t)m * N + bn + tx * 8];
        *reinterpret_cast<float4*>(cp)     = make_float4(o[0], o[1], o[2], o[3]);
        *reinterpret_cast<float4*>(cp + 4) = make_float4(o[4], o[5], o[6], o[7]);
    }
}

// ---------------------------------------------------------------------------
// Corner geometry (must match reference bit-for-bit semantics: fp32, rintf)
// ---------------------------------------------------------------------------
__device__ __forceinline__ void corner_calc(float c0, float c1, int cc,
                                            int& idx, float& rel0, float& rel1) {
    const float rr = 1.0f / 128.0f;
    float vx = (cc & 2) ? 1.f : -1.f;
    float vy = (cc & 1) ? 1.f : -1.f;
    float cy = fminf(fmaxf(c0 + vx * rr + 1e-6f, -1.f + 1e-6f), 1.f - 1e-6f);
    float cx = fminf(fmaxf(c1 + vy * rr + 1e-6f, -1.f + 1e-6f), 1.f - 1e-6f);
    int iy = (int)rintf(((cy + 1.0f) * 128.0f - 1.0f) * 0.5f);
    int ix = (int)rintf(((cx + 1.0f) * 128.0f - 1.0f) * 0.5f);
    iy = min(max(iy, 0), 127);
    ix = min(max(ix, 0), 127);
    float qy = -1.0f + (2.0f * (float)iy + 1.0f) / 128.0f;
    float qx = -1.0f + (2.0f * (float)ix + 1.0f) / 128.0f;
    rel0 = (c0 - qy) * 128.0f;
    rel1 = (c1 - qx) * 128.0f;
    idx = iy * 128 + ix;
}

// ---------------------------------------------------------------------------
// Kernel 4: assemble h1 = ReLU(hp[idx] + rel0*W0[585,:] + rel1*W0[586,:])
// grid (QN, 4), block 256
// ---------------------------------------------------------------------------
__global__ void assemble_h1(const float* __restrict__ hr, const float* __restrict__ W0) {
    int q = blockIdx.x;
    int cc = blockIdx.y;
    int j = threadIdx.x;
    float c0 = hr[2 * q], c1 = hr[2 * q + 1];
    int idx; float rel0, rel1;
    corner_calc(c0, c1, cc, idx, rel0, rel1);
    int s = cc * QN + q;
    float v = g_hp[idx * NH + j]
            + rel0 * W0[585 * NH + j]
            + rel1 * W0[586 * NH + j];
    g_bufA[(size_t)s * NH + j] = fmaxf(v, 0.f);
}

// ---------------------------------------------------------------------------
// Kernel 8: final layer (N=3), one warp per sample, input in g_bufB
// ---------------------------------------------------------------------------
__global__ void final_layer(const float* __restrict__ W4, const float* __restrict__ b4) {
    int warp = (blockIdx.x * blockDim.x + threadIdx.x) >> 5;
    int lane = threadIdx.x & 31;
    if (warp >= SN) return;
    const float* h = &g_bufB[(size_t)warp * NH];
    float a0 = 0.f, a1 = 0.f, a2 = 0.f;
#pragma unroll
    for (int t = 0; t < 8; t++) {
        int k = lane + 32 * t;
        float v = h[k];
        a0 += v * W4[k * 3 + 0];
        a1 += v * W4[k * 3 + 1];
        a2 += v * W4[k * 3 + 2];
    }
#pragma unroll
    for (int off = 16; off > 0; off >>= 1) {
        a0 += __shfl_down_sync(0xFFFFFFFFu, a0, off);
        a1 += __shfl_down_sync(0xFFFFFFFFu, a1, off);
        a2 += __shfl_down_sync(0xFFFFFFFFu, a2, off);
    }
    if (lane == 0) {
        g_pred[warp * 3 + 0] = a0 + b4[0];
        g_pred[warp * 3 + 1] = a1 + b4[1];
        g_pred[warp * 3 + 2] = a2 + b4[2];
    }
}

// ---------------------------------------------------------------------------
// Kernel 9: local ensemble (diagonal-swapped area weights), write [3,256,256]
// ---------------------------------------------------------------------------
__global__ void ensemble(const float* __restrict__ hr, float* __restrict__ out) {
    int q = blockIdx.x * blockDim.x + threadIdx.x;
    if (q >= QN) return;
    float c0 = hr[2 * q], c1 = hr[2 * q + 1];
    float area[4];
#pragma unroll
    for (int cc = 0; cc < 4; cc++) {
        int idx; float r0, r1;
        corner_calc(c0, c1, cc, idx, r0, r1);
        area[cc] = fabsf(r0 * r1) + 1e-9f;
    }
    float tot = area[0] + area[1] + area[2] + area[3];
    float o0 = 0.f, o1 = 0.f, o2 = 0.f;
#pragma unroll
    for (int cc = 0; cc < 4; cc++) {
        float w = area[3 - cc] / tot;   // local_ensemble swap 0<->3, 1<->2
        int s = cc * QN + q;
        o0 += g_pred[s * 3 + 0] * w;
        o1 += g_pred[s * 3 + 1] * w;
        o2 += g_pred[s * 3 + 2] * w;
    }
    out[0 * QN + q] = o0;
    out[1 * QN + q] = o1;
    out[2 * QN + q] = o2;
}

// ---------------------------------------------------------------------------
// Launch
// ---------------------------------------------------------------------------
extern "C" void kernel_launch(void* const* d_in, const int* in_sizes, int n_in,
                              void* d_out, int out_size) {
    const float* mf   = (const float*)d_in[0];
    const float* mask = (const float*)d_in[1];
    // d_in[2] = gt_feat (shape only, unused)
    const float* hr = (const float*)d_in[3];
    const float* W0 = (const float*)d_in[4];
    const float* b0 = (const float*)d_in[5];
    const float* W1 = (const float*)d_in[6];
    const float* b1 = (const float*)d_in[7];
    const float* W2 = (const float*)d_in[8];
    const float* b2 = (const float*)d_in[9];
    const float* W3 = (const float*)d_in[10];
    const float* b3 = (const float*)d_in[11];
    const float* W4 = (const float*)d_in[12];
    const float* b4 = (const float*)d_in[13];
    float* out = (float*)d_out;

    void *pX, *pW0p, *pHp, *pA, *pB;
    cudaGetSymbolAddress(&pX,   g_X);
    cudaGetSymbolAddress(&pW0p, g_W0p);
    cudaGetSymbolAddress(&pHp,  g_hp);
    cudaGetSymbolAddress(&pA,   g_bufA);
    cudaGetSymbolAddress(&pB,   g_bufB);

    build_X<<<NPIX, K1P>>>(mf, mask);
    pad_W0<<<(K1P * NH + 255) / 256, 256>>>(W0);

    // hp = X @ W0p + b0 (no relu)
    sgemm<<<dim3(NH / BN, NPIX / BM), 256>>>((const float*)pX, (const float*)pW0p,
                                             b0, (float*)pHp, NPIX, K1P, NH, 0);

    assemble_h1<<<dim3(QN, 4), 256>>>(hr, W0);

    // h2 = ReLU(h1 @ W1 + b1) ; h3 ; h4
    sgemm<<<dim3(NH / BN, SN / BM), 256>>>((const float*)pA, W1, b1, (float*)pB, SN, NH, NH, 1);
    sgemm<<<dim3(NH / BN, SN / BM), 256>>>((const float*)pB, W2, b2, (float*)pA, SN, NH, NH, 1);
    sgemm<<<dim3(NH / BN, SN / BM), 256>>>((const float*)pA, W3, b3, (float*)pB, SN, NH, NH, 1);

    final_layer<<<SN / 32, 1024>>>(W4, b4);
    ensemble<<<QN / 256, 256>>>(hr, out);
}

// round 3
// speedup vs baseline: 3.5836x; 3.5836x over previous
#include <cuda_runtime.h>
#include <cstdint>

// ---------------------------------------------------------------------------
// Problem constants
// ---------------------------------------------------------------------------
#define FH 128
#define FW 128
#define NPIX (FH*FW)       // 16384
#define QN 65536           // queries
#define SN (4*QN)          // 262144 corner samples
#define K1 585             // valid unfold dims
#define K0P 608            // padded K for layer0 (mult of 32)
#define NH 256

// ---------------------------------------------------------------------------
// Scratch
// ---------------------------------------------------------------------------
__device__ __align__(128) float g_X[NPIX * K0P];
__device__ __align__(128) float g_Wt0[NH * K0P];        // transposed, tf32-rounded
__device__ __align__(128) float g_Wt1[NH * NH];
__device__ __align__(128) float g_Wt2[NH * NH];
__device__ __align__(128) float g_Wt3[NH * NH];
__device__ __align__(128) float g_hp[NPIX * NH];
__device__ __align__(128) float g_bufA[(size_t)SN * NH];
__device__ __align__(128) float g_bufB[(size_t)SN * NH];
__device__ __align__(128) float g_pred[SN * 3];

// ---------------------------------------------------------------------------
// PTX helpers (all compute_103-portable: cp.async, ldmatrix, mma.sync)
// ---------------------------------------------------------------------------
__device__ __forceinline__ uint32_t smem_u32(const void* p) {
    uint32_t a;
    asm("{ .reg .u64 t; cvta.to.shared.u64 t, %1; cvt.u32.u64 %0, t; }" : "=r"(a) : "l"(p));
    return a;
}
__device__ __forceinline__ float rnd_tf32(float x) {
    uint32_t r;
    asm("cvt.rna.tf32.f32 %0, %1;" : "=r"(r) : "f"(x));
    return __uint_as_float(r);
}
__device__ __forceinline__ void cp16(uint32_t dst, const void* src) {
    asm volatile("cp.async.cg.shared.global [%0], [%1], 16;" :: "r"(dst), "l"(src));
}
#define CP_COMMIT() asm volatile("cp.async.commit_group;" ::: "memory")
#define CP_WAIT(n)  asm volatile("cp.async.wait_group %0;" :: "n"(n) : "memory")

__device__ __forceinline__ void ldsm4(uint32_t* r, uint32_t addr) {
    asm volatile("ldmatrix.sync.aligned.m8n8.x4.shared.b16 {%0,%1,%2,%3}, [%4];"
                 : "=r"(r[0]), "=r"(r[1]), "=r"(r[2]), "=r"(r[3]) : "r"(addr));
}
__device__ __forceinline__ void mma_tf32(float* d, const uint32_t* a, const uint32_t* b) {
    asm volatile(
        "mma.sync.aligned.m16n8k8.row.col.f32.tf32.tf32.f32 "
        "{%0,%1,%2,%3}, {%4,%5,%6,%7}, {%8,%9}, {%0,%1,%2,%3};"
        : "+f"(d[0]), "+f"(d[1]), "+f"(d[2]), "+f"(d[3])
        : "r"(a[0]), "r"(a[1]), "r"(a[2]), "r"(a[3]), "r"(b[0]), "r"(b[1]));
}

// ---------------------------------------------------------------------------
// GEMM: C[M,256] = A[M,K] @ Wt^T (+bias, relu?, tf32-round?)
//  A  [M,K]  row-major fp32 (tf32-rounded values)
//  Wt [256,K] row-major fp32 (transposed weight, tf32-rounded)
//  M % 128 == 0, K % 32 == 0. Grid: (M/128, 2). 256 threads.
//  Tile: BM=128, BN=128, BK=32. Warps 2(m) x 4(n); warp tile 64x32.
// SMEM: A stage 128x32 f32 (row 128B, chunk-XOR swizzle), 2 stages; B same.
// ---------------------------------------------------------------------------
#define AST 16384
#define SMEM_GEMM (4 * AST)

__device__ __forceinline__ void g_load_stage(uint32_t sb, const float* __restrict__ A,
                                             const float* __restrict__ Bt,
                                             size_t bm, int bn, int k0, int stg,
                                             int K, int tid) {
    uint32_t ab = sb + stg * AST;
    uint32_t bb = sb + 2 * AST + stg * AST;
#pragma unroll
    for (int i = 0; i < 4; i++) {
        int li = tid + i * 256;          // 0..1023
        int m = li >> 3, c = li & 7;
        cp16(ab + m * 128 + ((c ^ (m & 7)) << 4), A + (bm + m) * (size_t)K + k0 + c * 4);
    }
#pragma unroll
    for (int i = 0; i < 4; i++) {
        int li = tid + i * 256;
        int n = li >> 3, c = li & 7;
        cp16(bb + n * 128 + ((c ^ (n & 7)) << 4), Bt + (bn + n) * (size_t)K + k0 + c * 4);
    }
}

__global__ __launch_bounds__(256, 2) void gemm_mma(const float* __restrict__ A,
                                                   const float* __restrict__ Bt,
                                                   const float* __restrict__ bias,
                                                   float* __restrict__ C,
                                                   int K, int relu, int rnd) {
    extern __shared__ char smem[];
    uint32_t sb = smem_u32(smem);
    const int tid = threadIdx.x;
    const int wid = tid >> 5;
    const int lane = tid & 31;
    const int wm = wid >> 2;            // 0..1  (m dir, 64 rows)
    const int wn = wid & 3;             // 0..3  (n dir, 32 cols)
    const size_t bm = (size_t)blockIdx.x * 128;
    const int bn = blockIdx.y * 128;
    const int nit = K >> 5;

    float acc[4][4][4];
#pragma unroll
    for (int i = 0; i < 4; i++)
#pragma unroll
        for (int j = 0; j < 4; j++)
#pragma unroll
            for (int v = 0; v < 4; v++) acc[i][j][v] = 0.f;

    g_load_stage(sb, A, Bt, bm, bn, 0, 0, K, tid);
    CP_COMMIT();
    g_load_stage(sb, A, Bt, bm, bn, 32, 1, K, tid);
    CP_COMMIT();

    // precomputed ldmatrix lane geometry
    const int lr = lane & 7;            // row within 8
    const int sel = lane >> 3;          // quadrant 0..3
    // A: m_off = lr + (sel&1)*8 ; chunk c_off = (sel>>1)
    const int a_m = wm * 64 + lr + (sel & 1) * 8;
    const int a_c = sel >> 1;
    // B: n_off = lr + (sel>>1)*8 ; chunk c_off = (sel&1)
    const int b_n = wn * 32 + lr + (sel >> 1) * 8;
    const int b_c = sel & 1;

    for (int it = 0; it < nit; it++) {
        if (it + 1 < nit) { CP_WAIT(1); } else { CP_WAIT(0); }
        __syncthreads();

        uint32_t abase = sb + (it & 1) * AST;
        uint32_t bbase = sb + 2 * AST + (it & 1) * AST;

#pragma unroll
        for (int ks = 0; ks < 4; ks++) {
            uint32_t afr[4][4];
#pragma unroll
            for (int mt = 0; mt < 4; mt++) {
                int m = a_m + mt * 16;
                int c = ks * 2 + a_c;
                ldsm4(afr[mt], abase + m * 128 + ((c ^ (m & 7)) << 4));
            }
            uint32_t bfr[2][4];
#pragma unroll
            for (int g = 0; g < 2; g++) {
                int n = b_n + g * 16;
                int c = ks * 2 + b_c;
                ldsm4(bfr[g], bbase + n * 128 + ((c ^ (n & 7)) << 4));
            }
#pragma unroll
            for (int mt = 0; mt < 4; mt++)
#pragma unroll
                for (int nt = 0; nt < 4; nt++)
                    mma_tf32(acc[mt][nt], afr[mt], &bfr[nt >> 1][(nt & 1) * 2]);
        }

        __syncthreads();
        if (it + 2 < nit) {
            g_load_stage(sb, A, Bt, bm, bn, (it + 2) * 32, it & 1, K, tid);
            CP_COMMIT();
        }
    }

    // epilogue: c0,c1 at (row lane>>2, col 2*(lane&3)), c2,c3 at row+8
    const int er = lane >> 2;
    const int ec = (lane & 3) * 2;
#pragma unroll
    for (int mt = 0; mt < 4; mt++) {
#pragma unroll
        for (int nt = 0; nt < 4; nt++) {
            int n = bn + wn * 32 + nt * 8 + ec;
            float bi0 = __ldg(&bias[n]);
            float bi1 = __ldg(&bias[n + 1]);
            size_t m0 = bm + wm * 64 + mt * 16 + er;
            float v0 = acc[mt][nt][0] + bi0;
            float v1 = acc[mt][nt][1] + bi1;
            float v2 = acc[mt][nt][2] + bi0;
            float v3 = acc[mt][nt][3] + bi1;
            if (relu) {
                v0 = fmaxf(v0, 0.f); v1 = fmaxf(v1, 0.f);
                v2 = fmaxf(v2, 0.f); v3 = fmaxf(v3, 0.f);
            }
            if (rnd) {
                v0 = rnd_tf32(v0); v1 = rnd_tf32(v1);
                v2 = rnd_tf32(v2); v3 = rnd_tf32(v3);
            }
            *reinterpret_cast<float2*>(&C[m0 * 256 + n])       = make_float2(v0, v1);
            *reinterpret_cast<float2*>(&C[(m0 + 8) * 256 + n]) = make_float2(v2, v3);
        }
    }
}

// ---------------------------------------------------------------------------
// im2col, padded to K0P cols, tf32-rounded
// ---------------------------------------------------------------------------
__global__ void build_X(const float* __restrict__ mf, const float* __restrict__ mask) {
    int p = blockIdx.x;
    int t = threadIdx.x;
    if (t >= K0P) return;
    int y = p >> 7, x = p & 127;
    float v = 0.f;
    if (t < K1) {
        int c = t / 9, r = t - c * 9;
        int ki = r / 3, kj = r - ki * 3;
        int yy = y + ki - 1, xx = x + kj - 1;
        if (yy >= 0 && yy < FH && xx >= 0 && xx < FW) {
            v = (c < 64) ? mf[(c << 14) + (yy << 7) + xx] : mask[(yy << 7) + xx];
        }
        v = rnd_tf32(v);
    }
    g_X[p * K0P + t] = v;
}

// ---------------------------------------------------------------------------
// Transpose + tf32-round weights: Wt[n*Kp + k] = rnd(W[k*256 + n]) (0 if k>=Kv)
// ---------------------------------------------------------------------------
__global__ void prep_wt(const float* __restrict__ W, float* __restrict__ Wt,
                        int Kp, int Kv) {
    int i = blockIdx.x * blockDim.x + threadIdx.x;
    if (i >= 256 * Kp) return;
    int n = i / Kp, k = i - n * Kp;
    Wt[i] = (k < Kv) ? rnd_tf32(W[k * 256 + n]) : 0.f;
}

// ---------------------------------------------------------------------------
// Corner geometry (identical to passing round-1 semantics)
// ---------------------------------------------------------------------------
__device__ __forceinline__ void corner_calc(float c0, float c1, int cc,
                                            int& idx, float& rel0, float& rel1) {
    const float rr = 1.0f / 128.0f;
    float vx = (cc & 2) ? 1.f : -1.f;
    float vy = (cc & 1) ? 1.f : -1.f;
    float cy = fminf(fmaxf(c0 + vx * rr + 1e-6f, -1.f + 1e-6f), 1.f - 1e-6f);
    float cx = fminf(fmaxf(c1 + vy * rr + 1e-6f, -1.f + 1e-6f), 1.f - 1e-6f);
    int iy = (int)rintf(((cy + 1.0f) * 128.0f - 1.0f) * 0.5f);
    int ix = (int)rintf(((cx + 1.0f) * 128.0f - 1.0f) * 0.5f);
    iy = min(max(iy, 0), 127);
    ix = min(max(ix, 0), 127);
    float qy = -1.0f + (2.0f * (float)iy + 1.0f) / 128.0f;
    float qx = -1.0f + (2.0f * (float)ix + 1.0f) / 128.0f;
    rel0 = (c0 - qy) * 128.0f;
    rel1 = (c1 - qx) * 128.0f;
    idx = iy * 128 + ix;
}

// ---------------------------------------------------------------------------
// assemble: h1 = rnd(ReLU(hp[idx] + rel0*W0[585,:] + rel1*W0[586,:]))
// grid QN, block 128 (warp = corner)
// ---------------------------------------------------------------------------
__global__ __launch_bounds__(128) void assemble_h1(const float* __restrict__ hr,
                                                   const float* __restrict__ W0) {
    int q = blockIdx.x;
    int wid = threadIdx.x >> 5;
    int lane = threadIdx.x & 31;
    int idx = 0;
    float r0 = 0.f, r1 = 0.f;
    if (lane == 0) {
        float c0 = hr[2 * q], c1 = hr[2 * q + 1];
        corner_calc(c0, c1, wid, idx, r0, r1);
    }
    idx = __shfl_sync(0xFFFFFFFFu, idx, 0);
    r0 = __shfl_sync(0xFFFFFFFFu, r0, 0);
    r1 = __shfl_sync(0xFFFFFFFFu, r1, 0);

    const float4* hp4 = (const float4*)(g_hp + (size_t)idx * NH);
    const float4* wa = (const float4*)(W0 + 585 * NH);
    const float4* wb = (const float4*)(W0 + 586 * NH);
    size_t s = (size_t)wid * QN + q;
    float4* dst = (float4*)(g_bufA + s * NH);
#pragma unroll
    for (int j = lane; j < 64; j += 32) {
        float4 h = hp4[j], a = __ldg(&wa[j]), b = __ldg(&wb[j]);
        float4 o;
        o.x = rnd_tf32(fmaxf(h.x + r0 * a.x + r1 * b.x, 0.f));
        o.y = rnd_tf32(fmaxf(h.y + r0 * a.y + r1 * b.y, 0.f));
        o.z = rnd_tf32(fmaxf(h.z + r0 * a.z + r1 * b.z, 0.f));
        o.w = rnd_tf32(fmaxf(h.w + r0 * a.w + r1 * b.w, 0.f));
        dst[j] = o;
    }
}

// ---------------------------------------------------------------------------
// final layer (N=3), one warp per sample, input g_bufB (fp32)
// ---------------------------------------------------------------------------
__global__ void final_layer(const float* __restrict__ W4, const float* __restrict__ b4) {
    int warp = (blockIdx.x * blockDim.x + threadIdx.x) >> 5;
    int lane = threadIdx.x & 31;
    if (warp >= SN) return;
    const float* h = &g_bufB[(size_t)warp * NH];
    float a0 = 0.f, a1 = 0.f, a2 = 0.f;
#pragma unroll
    for (int t = 0; t < 8; t++) {
        int k = lane + 32 * t;
        float v = h[k];
        a0 += v * W4[k * 3 + 0];
        a1 += v * W4[k * 3 + 1];
        a2 += v * W4[k * 3 + 2];
    }
#pragma unroll
    for (int off = 16; off > 0; off >>= 1) {
        a0 += __shfl_down_sync(0xFFFFFFFFu, a0, off);
        a1 += __shfl_down_sync(0xFFFFFFFFu, a1, off);
        a2 += __shfl_down_sync(0xFFFFFFFFu, a2, off);
    }
    if (lane == 0) {
        g_pred[warp * 3 + 0] = a0 + b4[0];
        g_pred[warp * 3 + 1] = a1 + b4[1];
        g_pred[warp * 3 + 2] = a2 + b4[2];
    }
}

// ---------------------------------------------------------------------------
// local ensemble
// ---------------------------------------------------------------------------
__global__ void ensemble(const float* __restrict__ hr, float* __restrict__ out) {
    int q = blockIdx.x * blockDim.x + threadIdx.x;
    if (q >= QN) return;
    float c0 = hr[2 * q], c1 = hr[2 * q + 1];
    float area[4];
#pragma unroll
    for (int cc = 0; cc < 4; cc++) {
        int idx; float r0, r1;
        corner_calc(c0, c1, cc, idx, r0, r1);
        area[cc] = fabsf(r0 * r1) + 1e-9f;
    }
    float tot = area[0] + area[1] + area[2] + area[3];
    float o0 = 0.f, o1 = 0.f, o2 = 0.f;
#pragma unroll
    for (int cc = 0; cc < 4; cc++) {
        float w = area[3 - cc] / tot;
        size_t s = (size_t)cc * QN + q;
        o0 += g_pred[s * 3 + 0] * w;
        o1 += g_pred[s * 3 + 1] * w;
        o2 += g_pred[s * 3 + 2] * w;
    }
    out[0 * QN + q] = o0;
    out[1 * QN + q] = o1;
    out[2 * QN + q] = o2;
}

// ---------------------------------------------------------------------------
// Launch
// ---------------------------------------------------------------------------
extern "C" void kernel_launch(void* const* d_in, const int* in_sizes, int n_in,
                              void* d_out, int out_size) {
    const float* mf   = (const float*)d_in[0];
    const float* mask = (const float*)d_in[1];
    const float* hr = (const float*)d_in[3];
    const float* W0 = (const float*)d_in[4];
    const float* b0 = (const float*)d_in[5];
    const float* W1 = (const float*)d_in[6];
    const float* b1 = (const float*)d_in[7];
    const float* W2 = (const float*)d_in[8];
    const float* b2 = (const float*)d_in[9];
    const float* W3 = (const float*)d_in[10];
    const float* b3 = (const float*)d_in[11];
    const float* W4 = (const float*)d_in[12];
    const float* b4 = (const float*)d_in[13];
    float* out = (float*)d_out;

    void *pX, *pWt0, *pWt1, *pWt2, *pWt3, *pHp, *pA, *pB;
    cudaGetSymbolAddress(&pX,   g_X);
    cudaGetSymbolAddress(&pWt0, g_Wt0);
    cudaGetSymbolAddress(&pWt1, g_Wt1);
    cudaGetSymbolAddress(&pWt2, g_Wt2);
    cudaGetSymbolAddress(&pWt3, g_Wt3);
    cudaGetSymbolAddress(&pHp,  g_hp);
    cudaGetSymbolAddress(&pA,   g_bufA);
    cudaGetSymbolAddress(&pB,   g_bufB);

    cudaFuncSetAttribute(gemm_mma, cudaFuncAttributeMaxDynamicSharedMemorySize, SMEM_GEMM);

    build_X<<<NPIX, 640>>>(mf, mask);
    prep_wt<<<(256 * K0P + 255) / 256, 256>>>(W0, (float*)pWt0, K0P, K1);
    prep_wt<<<(256 * 256 + 255) / 256, 256>>>(W1, (float*)pWt1, 256, 256);
    prep_wt<<<(256 * 256 + 255) / 256, 256>>>(W2, (float*)pWt2, 256, 256);
    prep_wt<<<(256 * 256 + 255) / 256, 256>>>(W3, (float*)pWt3, 256, 256);

    // hp = X @ W0 + b0 (no relu, no round)
    gemm_mma<<<dim3(NPIX / 128, 2), 256, SMEM_GEMM>>>((const float*)pX, (const float*)pWt0,
                                                      b0, (float*)pHp, K0P, 0, 0);

    assemble_h1<<<QN, 128>>>(hr, W0);

    gemm_mma<<<dim3(SN / 128, 2), 256, SMEM_GEMM>>>((const float*)pA, (const float*)pWt1,
                                                    b1, (float*)pB, 256, 1, 1);
    gemm_mma<<<dim3(SN / 128, 2), 256, SMEM_GEMM>>>((const float*)pB, (const float*)pWt2,
                                                    b2, (float*)pA, 256, 1, 1);
    gemm_mma<<<dim3(SN / 128, 2), 256, SMEM_GEMM>>>((const float*)pA, (const float*)pWt3,
                                                    b3, (float*)pB, 256, 1, 0);

    final_layer<<<SN / 32, 1024>>>(W4, b4);
    ensemble<<<QN / 256, 256>>>(hr, out);
}

// round 6
// speedup vs baseline: 3.7297x; 1.0408x over previous
#include <cuda_runtime.h>
#include <cstdint>

// ---------------------------------------------------------------------------
// Problem constants
// ---------------------------------------------------------------------------
#define FH 128
#define FW 128
#define NPIX (FH*FW)       // 16384
#define QN 65536           // queries
#define SN (4*QN)          // 262144 corner samples
#define K1 585             // valid unfold dims
#define K0P 608            // padded K for layer0 (mult of 32)
#define NH 256

// ---------------------------------------------------------------------------
// Scratch (fp32 everywhere — proven path)
// ---------------------------------------------------------------------------
__device__ __align__(128) float g_X[NPIX * K0P];
__device__ __align__(128) float g_Wt0[NH * K0P];
__device__ __align__(128) float g_Wt1[NH * NH];
__device__ __align__(128) float g_Wt2[NH * NH];
__device__ __align__(128) float g_Wt3[NH * NH];
__device__ __align__(128) float g_hp[NPIX * NH];
__device__ __align__(128) float g_bufA[(size_t)SN * NH];
__device__ __align__(128) float g_bufB[(size_t)SN * NH];
__device__ __align__(128) float g_pred[SN * 3];

// ---------------------------------------------------------------------------
// PTX helpers (compute_103-portable: cp.async, ldmatrix, mma.sync) — R3-proven
// ---------------------------------------------------------------------------
__device__ __forceinline__ uint32_t smem_u32(const void* p) {
    uint32_t a;
    asm("{ .reg .u64 t; cvta.to.shared.u64 t, %1; cvt.u32.u64 %0, t; }" : "=r"(a) : "l"(p));
    return a;
}
__device__ __forceinline__ float rnd_tf32(float x) {
    uint32_t r;
    asm("cvt.rna.tf32.f32 %0, %1;" : "=r"(r) : "f"(x));
    return __uint_as_float(r);
}
__device__ __forceinline__ void cp16(uint32_t dst, const void* src) {
    asm volatile("cp.async.cg.shared.global [%0], [%1], 16;" :: "r"(dst), "l"(src));
}
#define CP_COMMIT() asm volatile("cp.async.commit_group;" ::: "memory")
#define CP_WAIT(n)  asm volatile("cp.async.wait_group %0;" :: "n"(n) : "memory")

__device__ __forceinline__ void ldsm4(uint32_t* r, uint32_t addr) {
    asm volatile("ldmatrix.sync.aligned.m8n8.x4.shared.b16 {%0,%1,%2,%3}, [%4];"
                 : "=r"(r[0]), "=r"(r[1]), "=r"(r[2]), "=r"(r[3]) : "r"(addr));
}
__device__ __forceinline__ void mma_tf32(float* d, const uint32_t* a, const uint32_t* b) {
    asm volatile(
        "mma.sync.aligned.m16n8k8.row.col.f32.tf32.tf32.f32 "
        "{%0,%1,%2,%3}, {%4,%5,%6,%7}, {%8,%9}, {%0,%1,%2,%3};"
        : "+f"(d[0]), "+f"(d[1]), "+f"(d[2]), "+f"(d[3])
        : "r"(a[0]), "r"(a[1]), "r"(a[2]), "r"(a[3]), "r"(b[0]), "r"(b[1]));
}

// ---------------------------------------------------------------------------
// Shared GEMM geometry (R3-proven): BM=128, BN=128, BK=32, 256 thr, 2x4 warps
// Stage = 128 rows x 128B, chunk-XOR swizzle.
// ---------------------------------------------------------------------------
#define AST 16384
#define SMEM_GEMM (4 * AST)
#define SMEM_L1   (4 * AST + 1536)   // + idx/r0/r1 for 128 rows
#define SMEM_L3   (4 * AST + 3072)   // + W4 [256][3]

__device__ __forceinline__ uint32_t swzo(int r, int c) {   // byte offset in stage
    return (uint32_t)(r * 128 + ((c ^ (r & 7)) << 4));
}

__device__ __forceinline__ void g_load_stage(uint32_t sb, const float* __restrict__ A,
                                             const float* __restrict__ Bt,
                                             size_t bm, int bn, int k0, int stg,
                                             int K, int tid) {
    uint32_t ab = sb + stg * AST;
    uint32_t bb = sb + 2 * AST + stg * AST;
#pragma unroll
    for (int i = 0; i < 4; i++) {
        int li = tid + i * 256;          // 0..1023
        int m = li >> 3, c = li & 7;
        cp16(ab + swzo(m, c), A + (bm + m) * (size_t)K + k0 + c * 4);
    }
#pragma unroll
    for (int i = 0; i < 4; i++) {
        int li = tid + i * 256;
        int n = li >> 3, c = li & 7;
        cp16(bb + swzo(n, c), Bt + (size_t)(bn + n) * K + k0 + c * 4);
    }
}

__device__ __forceinline__ void g_load_B(uint32_t sb, const float* __restrict__ Bt,
                                         int bn, int k0, int stg, int K, int tid) {
    uint32_t bb = sb + 2 * AST + stg * AST;
#pragma unroll
    for (int i = 0; i < 4; i++) {
        int li = tid + i * 256;
        int n = li >> 3, c = li & 7;
        cp16(bb + swzo(n, c), Bt + (size_t)(bn + n) * K + k0 + c * 4);
    }
}

// MMA mainloop body macro params precomputed per-thread
struct LdsmGeom {
    int a_r, a_c, b_r, b_c;
};
__device__ __forceinline__ LdsmGeom make_geom(int lane, int wm, int wn) {
    LdsmGeom g;
    int rw = lane & 7;
    int j  = lane >> 3;
    g.a_r = wm * 64 + rw + (j & 1) * 8;
    g.a_c = j >> 1;
    g.b_r = wn * 32 + rw + (j >> 1) * 8;
    g.b_c = j & 1;
    return g;
}

__device__ __forceinline__ void mma_block(float acc[4][4][4], uint32_t abase,
                                          uint32_t bbase, const LdsmGeom& g) {
#pragma unroll
    for (int ks = 0; ks < 4; ks++) {
        uint32_t afr[4][4];
#pragma unroll
        for (int mt = 0; mt < 4; mt++) {
            int m = g.a_r + mt * 16;
            int c = ks * 2 + g.a_c;
            ldsm4(afr[mt], abase + swzo(m, c));
        }
        uint32_t bfr[2][4];
#pragma unroll
        for (int gg = 0; gg < 2; gg++) {
            int n = g.b_r + gg * 16;
            int c = ks * 2 + g.b_c;
            ldsm4(bfr[gg], bbase + swzo(n, c));
        }
#pragma unroll
        for (int mt = 0; mt < 4; mt++)
#pragma unroll
            for (int nt = 0; nt < 4; nt++)
                mma_tf32(acc[mt][nt], afr[mt], &bfr[nt >> 1][(nt & 1) * 2]);
    }
}

// ---------------------------------------------------------------------------
// Generic GEMM (R3-proven): C[M,256] = A[M,K] @ Wt^T (+bias, relu?, rnd?)
// ---------------------------------------------------------------------------
__global__ __launch_bounds__(256, 2) void gemm_tf32(const float* __restrict__ A,
                                                    const float* __restrict__ Bt,
                                                    const float* __restrict__ bias,
                                                    float* __restrict__ C,
                                                    int K, int relu, int rnd) {
    extern __shared__ char smem[];
    uint32_t sb = smem_u32(smem);
    const int tid = threadIdx.x;
    const int wid = tid >> 5;
    const int lane = tid & 31;
    const int wm = wid >> 2;
    const int wn = wid & 3;
    const size_t bm = (size_t)blockIdx.x * 128;
    const int bn = blockIdx.y * 128;
    const int nit = K >> 5;

    float acc[4][4][4];
#pragma unroll
    for (int i = 0; i < 4; i++)
#pragma unroll
        for (int j = 0; j < 4; j++)
#pragma unroll
            for (int v = 0; v < 4; v++) acc[i][j][v] = 0.f;

    g_load_stage(sb, A, Bt, bm, bn, 0, 0, K, tid);
    CP_COMMIT();
    g_load_stage(sb, A, Bt, bm, bn, 32, 1, K, tid);
    CP_COMMIT();

    LdsmGeom geo = make_geom(lane, wm, wn);

    for (int it = 0; it < nit; it++) {
        if (it + 1 < nit) { CP_WAIT(1); } else { CP_WAIT(0); }
        __syncthreads();
        mma_block(acc, sb + (it & 1) * AST, sb + 2 * AST + (it & 1) * AST, geo);
        __syncthreads();
        if (it + 2 < nit) {
            g_load_stage(sb, A, Bt, bm, bn, (it + 2) * 32, it & 1, K, tid);
            CP_COMMIT();
        }
    }

    const int er = lane >> 2;
    const int ec = (lane & 3) * 2;
#pragma unroll
    for (int mt = 0; mt < 4; mt++) {
#pragma unroll
        for (int nt = 0; nt < 4; nt++) {
            int n = bn + wn * 32 + nt * 8 + ec;
            float bi0 = __ldg(&bias[n]);
            float bi1 = __ldg(&bias[n + 1]);
            size_t m0 = bm + wm * 64 + mt * 16 + er;
            float v0 = acc[mt][nt][0] + bi0;
            float v1 = acc[mt][nt][1] + bi1;
            float v2 = acc[mt][nt][2] + bi0;
            float v3 = acc[mt][nt][3] + bi1;
            if (relu) {
                v0 = fmaxf(v0, 0.f); v1 = fmaxf(v1, 0.f);
                v2 = fmaxf(v2, 0.f); v3 = fmaxf(v3, 0.f);
            }
            if (rnd) {
                v0 = rnd_tf32(v0); v1 = rnd_tf32(v1);
                v2 = rnd_tf32(v2); v3 = rnd_tf32(v3);
            }
            *reinterpret_cast<float2*>(&C[m0 * 256 + n])       = make_float2(v0, v1);
            *reinterpret_cast<float2*>(&C[(m0 + 8) * 256 + n]) = make_float2(v2, v3);
        }
    }
}

// ---------------------------------------------------------------------------
// Corner geometry (proven)
// ---------------------------------------------------------------------------
__device__ __forceinline__ void corner_calc(float c0, float c1, int cc,
                                            int& idx, float& rel0, float& rel1) {
    const float rr = 1.0f / 128.0f;
    float vx = (cc & 2) ? 1.f : -1.f;
    float vy = (cc & 1) ? 1.f : -1.f;
    float cy = fminf(fmaxf(c0 + vx * rr + 1e-6f, -1.f + 1e-6f), 1.f - 1e-6f);
    float cx = fminf(fmaxf(c1 + vy * rr + 1e-6f, -1.f + 1e-6f), 1.f - 1e-6f);
    int iy = (int)rintf(((cy + 1.0f) * 128.0f - 1.0f) * 0.5f);
    int ix = (int)rintf(((cx + 1.0f) * 128.0f - 1.0f) * 0.5f);
    iy = min(max(iy, 0), 127);
    ix = min(max(ix, 0), 127);
    float qy = -1.0f + (2.0f * (float)iy + 1.0f) / 128.0f;
    float qx = -1.0f + (2.0f * (float)ix + 1.0f) / 128.0f;
    rel0 = (c0 - qy) * 128.0f;
    rel1 = (c1 - qx) * 128.0f;
    idx = iy * 128 + ix;
}

// ---------------------------------------------------------------------------
// Layer-1 GEMM with fused assemble: A[s,k] = rnd(relu(hp[idx_s][k]
//   + r0_s*W0[585][k] + r1_s*W0[586][k])); C = A @ Wt1^T + b1, relu, rnd.
// A is materialized directly into smem stages (no gmem A, no assemble kernel).
// ---------------------------------------------------------------------------
__device__ __forceinline__ void fill_A_l1(char* smem, const int* sIdx,
                                          const float* sR0, const float* sR1,
                                          const float* __restrict__ W0,
                                          int k0, int stg, int tid) {
#pragma unroll
    for (int i = 0; i < 4; i++) {
        int li = tid + i * 256;          // 0..1023
        int m = li >> 3, c = li & 7;
        int row = sIdx[m];
        float r0 = sR0[m], r1 = sR1[m];
        float4 h  = __ldg((const float4*)&g_hp[(size_t)row * NH + k0 + c * 4]);
        float4 wa = __ldg((const float4*)&W0[585 * NH + k0 + c * 4]);
        float4 wb = __ldg((const float4*)&W0[586 * NH + k0 + c * 4]);
        float4 o;
        o.x = rnd_tf32(fmaxf(h.x + r0 * wa.x + r1 * wb.x, 0.f));
        o.y = rnd_tf32(fmaxf(h.y + r0 * wa.y + r1 * wb.y, 0.f));
        o.z = rnd_tf32(fmaxf(h.z + r0 * wa.z + r1 * wb.z, 0.f));
        o.w = rnd_tf32(fmaxf(h.w + r0 * wa.w + r1 * wb.w, 0.f));
        *reinterpret_cast<float4*>(smem + stg * AST + swzo(m, c)) = o;
    }
}

__global__ __launch_bounds__(256, 2) void gemm_l1(const float* __restrict__ hr,
                                                  const float* __restrict__ W0,
                                                  const float* __restrict__ Bt,
                                                  const float* __restrict__ bias,
                                                  float* __restrict__ C) {
    extern __shared__ char smem[];
    uint32_t sb = smem_u32(smem);
    int*   sIdx = (int*)(smem + 4 * AST);
    float* sR0  = (float*)(smem + 4 * AST + 512);
    float* sR1  = (float*)(smem + 4 * AST + 1024);
    const int tid = threadIdx.x;
    const int wid = tid >> 5;
    const int lane = tid & 31;
    const int wm = wid >> 2;
    const int wn = wid & 3;
    const size_t bm = (size_t)blockIdx.x * 128;
    const int bn = blockIdx.y * 128;
    const int K = NH;                 // 256
    const int nit = K >> 5;           // 8

    if (tid < 128) {
        size_t s = bm + tid;
        int cc = (int)(s >> 16);      // QN = 65536
        int q  = (int)(s & 65535);
        float c0 = hr[2 * q], c1 = hr[2 * q + 1];
        int idx; float r0, r1;
        corner_calc(c0, c1, cc, idx, r0, r1);
        sIdx[tid] = idx; sR0[tid] = r0; sR1[tid] = r1;
    }
    __syncthreads();

    float acc[4][4][4];
#pragma unroll
    for (int i = 0; i < 4; i++)
#pragma unroll
        for (int j = 0; j < 4; j++)
#pragma unroll
            for (int v = 0; v < 4; v++) acc[i][j][v] = 0.f;

    fill_A_l1(smem, sIdx, sR0, sR1, W0, 0, 0, tid);
    g_load_B(sb, Bt, bn, 0, 0, K, tid);
    CP_COMMIT();
    fill_A_l1(smem, sIdx, sR0, sR1, W0, 32, 1, tid);
    g_load_B(sb, Bt, bn, 32, 1, K, tid);
    CP_COMMIT();

    LdsmGeom geo = make_geom(lane, wm, wn);

    for (int it = 0; it < nit; it++) {
        if (it + 1 < nit) { CP_WAIT(1); } else { CP_WAIT(0); }
        __syncthreads();
        mma_block(acc, sb + (it & 1) * AST, sb + 2 * AST + (it & 1) * AST, geo);
        __syncthreads();
        if (it + 2 < nit) {
            fill_A_l1(smem, sIdx, sR0, sR1, W0, (it + 2) * 32, it & 1, tid);
            g_load_B(sb, Bt, bn, (it + 2) * 32, it & 1, K, tid);
            CP_COMMIT();
        }
    }

    const int er = lane >> 2;
    const int ec = (lane & 3) * 2;
#pragma unroll
    for (int mt = 0; mt < 4; mt++) {
#pragma unroll
        for (int nt = 0; nt < 4; nt++) {
            int n = bn + wn * 32 + nt * 8 + ec;
            float bi0 = __ldg(&bias[n]);
            float bi1 = __ldg(&bias[n + 1]);
            size_t m0 = bm + wm * 64 + mt * 16 + er;
            float v0 = rnd_tf32(fmaxf(acc[mt][nt][0] + bi0, 0.f));
            float v1 = rnd_tf32(fmaxf(acc[mt][nt][1] + bi1, 0.f));
            float v2 = rnd_tf32(fmaxf(acc[mt][nt][2] + bi0, 0.f));
            float v3 = rnd_tf32(fmaxf(acc[mt][nt][3] + bi1, 0.f));
            *reinterpret_cast<float2*>(&C[m0 * 256 + n])       = make_float2(v0, v1);
            *reinterpret_cast<float2*>(&C[(m0 + 8) * 256 + n]) = make_float2(v2, v3);
        }
    }
}

// ---------------------------------------------------------------------------
// Layer-3 GEMM with fused final layer: h4 = relu(A @ Wt3^T + b3);
// atomicAdd(g_pred[m][c] , sum_n h4[m][n] * W4[n][c])   (b4 added in ensemble)
// ---------------------------------------------------------------------------
__global__ __launch_bounds__(256, 2) void gemm_l3(const float* __restrict__ A,
                                                  const float* __restrict__ Bt,
                                                  const float* __restrict__ bias,
                                                  const float* __restrict__ W4) {
    extern __shared__ char smem[];
    uint32_t sb = smem_u32(smem);
    float* sW4 = (float*)(smem + 4 * AST);      // [256][3]
    const int tid = threadIdx.x;
    const int wid = tid >> 5;
    const int lane = tid & 31;
    const int wm = wid >> 2;
    const int wn = wid & 3;
    const size_t bm = (size_t)blockIdx.x * 128;
    const int bn = blockIdx.y * 128;
    const int K = NH;
    const int nit = K >> 5;

    if (tid < 256) {
        sW4[tid * 3 + 0] = W4[tid * 3 + 0];
        sW4[tid * 3 + 1] = W4[tid * 3 + 1];
        sW4[tid * 3 + 2] = W4[tid * 3 + 2];
    }
    __syncthreads();

    float acc[4][4][4];
#pragma unroll
    for (int i = 0; i < 4; i++)
#pragma unroll
        for (int j = 0; j < 4; j++)
#pragma unroll
            for (int v = 0; v < 4; v++) acc[i][j][v] = 0.f;

    g_load_stage(sb, A, Bt, bm, bn, 0, 0, K, tid);
    CP_COMMIT();
    g_load_stage(sb, A, Bt, bm, bn, 32, 1, K, tid);
    CP_COMMIT();

    LdsmGeom geo = make_geom(lane, wm, wn);

    for (int it = 0; it < nit; it++) {
        if (it + 1 < nit) { CP_WAIT(1); } else { CP_WAIT(0); }
        __syncthreads();
        mma_block(acc, sb + (it & 1) * AST, sb + 2 * AST + (it & 1) * AST, geo);
        __syncthreads();
        if (it + 2 < nit) {
            g_load_stage(sb, A, Bt, bm, bn, (it + 2) * 32, it & 1, K, tid);
            CP_COMMIT();
        }
    }

    // fused epilogue: per-row partial 3-vector, quad-reduced, atomics
    const int er = lane >> 2;
    const int ec = (lane & 3) * 2;
#pragma unroll
    for (int mt = 0; mt < 4; mt++) {
        float p[2][3];
#pragma unroll
        for (int h = 0; h < 2; h++)
#pragma unroll
            for (int c = 0; c < 3; c++) p[h][c] = 0.f;
#pragma unroll
        for (int nt = 0; nt < 4; nt++) {
            int n = bn + wn * 32 + nt * 8 + ec;
            float bi0 = __ldg(&bias[n]);
            float bi1 = __ldg(&bias[n + 1]);
            float v0 = fmaxf(acc[mt][nt][0] + bi0, 0.f);
            float v1 = fmaxf(acc[mt][nt][1] + bi1, 0.f);
            float v2 = fmaxf(acc[mt][nt][2] + bi0, 0.f);
            float v3 = fmaxf(acc[mt][nt][3] + bi1, 0.f);
#pragma unroll
            for (int c = 0; c < 3; c++) {
                float w0 = sW4[n * 3 + c];
                float w1 = sW4[(n + 1) * 3 + c];
                p[0][c] += v0 * w0 + v1 * w1;
                p[1][c] += v2 * w0 + v3 * w1;
            }
        }
#pragma unroll
        for (int h = 0; h < 2; h++)
#pragma unroll
            for (int c = 0; c < 3; c++) {
                p[h][c] += __shfl_xor_sync(0xFFFFFFFFu, p[h][c], 1);
                p[h][c] += __shfl_xor_sync(0xFFFFFFFFu, p[h][c], 2);
            }
        if ((lane & 3) == 0) {
            size_t m0 = bm + wm * 64 + mt * 16 + er;
#pragma unroll
            for (int c = 0; c < 3; c++) {
                atomicAdd(&g_pred[m0 * 3 + c],       p[0][c]);
                atomicAdd(&g_pred[(m0 + 8) * 3 + c], p[1][c]);
            }
        }
    }
}

// ---------------------------------------------------------------------------
// im2col (padded, tf32-rounded) + weight transpose — R3-proven
// ---------------------------------------------------------------------------
__global__ void build_X(const float* __restrict__ mf, const float* __restrict__ mask) {
    int p = blockIdx.x;
    int t = threadIdx.x;
    if (t >= K0P) return;
    int y = p >> 7, x = p & 127;
    float v = 0.f;
    if (t < K1) {
        int c = t / 9, r = t - c * 9;
        int ki = r / 3, kj = r - ki * 3;
        int yy = y + ki - 1, xx = x + kj - 1;
        if (yy >= 0 && yy < FH && xx >= 0 && xx < FW) {
            v = (c < 64) ? mf[(c << 14) + (yy << 7) + xx] : mask[(yy << 7) + xx];
        }
        v = rnd_tf32(v);
    }
    g_X[p * K0P + t] = v;
}

__global__ void prep_wt(const float* __restrict__ W, float* __restrict__ Wt,
                        int Kp, int Kv) {
    int i = blockIdx.x * blockDim.x + threadIdx.x;
    if (i >= 256 * Kp) return;
    int n = i / Kp, k = i - n * Kp;
    Wt[i] = (k < Kv) ? rnd_tf32(W[k * 256 + n]) : 0.f;
}

__global__ void zero_pred() {
    int i = blockIdx.x * blockDim.x + threadIdx.x;
    if (i < SN * 3) g_pred[i] = 0.f;
}

// ---------------------------------------------------------------------------
// local ensemble (adds b4 here since gemm_l3 accumulates only the dot part)
// ---------------------------------------------------------------------------
__global__ void ensemble(const float* __restrict__ hr, const float* __restrict__ b4,
                         float* __restrict__ out) {
    int q = blockIdx.x * blockDim.x + threadIdx.x;
    if (q >= QN) return;
    float c0 = hr[2 * q], c1 = hr[2 * q + 1];
    float b40 = __ldg(&b4[0]), b41 = __ldg(&b4[1]), b42 = __ldg(&b4[2]);
    float area[4];
#pragma unroll
    for (int cc = 0; cc < 4; cc++) {
        int idx; float r0, r1;
        corner_calc(c0, c1, cc, idx, r0, r1);
        area[cc] = fabsf(r0 * r1) + 1e-9f;
    }
    float tot = area[0] + area[1] + area[2] + area[3];
    float o0 = 0.f, o1 = 0.f, o2 = 0.f;
#pragma unroll
    for (int cc = 0; cc < 4; cc++) {
        float w = area[3 - cc] / tot;
        size_t s = (size_t)cc * QN + q;
        o0 += (g_pred[s * 3 + 0] + b40) * w;
        o1 += (g_pred[s * 3 + 1] + b41) * w;
        o2 += (g_pred[s * 3 + 2] + b42) * w;
    }
    out[0 * QN + q] = o0;
    out[1 * QN + q] = o1;
    out[2 * QN + q] = o2;
}

// ---------------------------------------------------------------------------
// Launch
// ---------------------------------------------------------------------------
extern "C" void kernel_launch(void* const* d_in, const int* in_sizes, int n_in,
                              void* d_out, int out_size) {
    const float* mf   = (const float*)d_in[0];
    const float* mask = (const float*)d_in[1];
    const float* hr = (const float*)d_in[3];
    const float* W0 = (const float*)d_in[4];
    const float* b0 = (const float*)d_in[5];
    const float* W1 = (const float*)d_in[6];
    const float* b1 = (const float*)d_in[7];
    const float* W2 = (const float*)d_in[8];
    const float* b2 = (const float*)d_in[9];
    const float* W3 = (const float*)d_in[10];
    const float* b3 = (const float*)d_in[11];
    const float* W4 = (const float*)d_in[12];
    const float* b4 = (const float*)d_in[13];
    float* out = (float*)d_out;

    void *pX, *pWt0, *pWt1, *pWt2, *pWt3, *pHp, *pA, *pB;
    cudaGetSymbolAddress(&pX,   g_X);
    cudaGetSymbolAddress(&pWt0, g_Wt0);
    cudaGetSymbolAddress(&pWt1, g_Wt1);
    cudaGetSymbolAddress(&pWt2, g_Wt2);
    cudaGetSymbolAddress(&pWt3, g_Wt3);
    cudaGetSymbolAddress(&pHp,  g_hp);
    cudaGetSymbolAddress(&pA,   g_bufA);
    cudaGetSymbolAddress(&pB,   g_bufB);

    cudaFuncSetAttribute(gemm_tf32, cudaFuncAttributeMaxDynamicSharedMemorySize, SMEM_GEMM);
    cudaFuncSetAttribute(gemm_l1,   cudaFuncAttributeMaxDynamicSharedMemorySize, SMEM_L1);
    cudaFuncSetAttribute(gemm_l3,   cudaFuncAttributeMaxDynamicSharedMemorySize, SMEM_L3);

    build_X<<<NPIX, 640>>>(mf, mask);
    prep_wt<<<(256 * K0P + 255) / 256, 256>>>(W0, (float*)pWt0, K0P, K1);
    prep_wt<<<(256 * 256 + 255) / 256, 256>>>(W1, (float*)pWt1, 256, 256);
    prep_wt<<<(256 * 256 + 255) / 256, 256>>>(W2, (float*)pWt2, 256, 256);
    prep_wt<<<(256 * 256 + 255) / 256, 256>>>(W3, (float*)pWt3, 256, 256);
    zero_pred<<<(SN * 3 + 255) / 256, 256>>>();

    // hp = X @ W0 + b0 (no relu, no round)
    gemm_tf32<<<dim3(NPIX / 128, 2), 256, SMEM_GEMM>>>((const float*)pX, (const float*)pWt0,
                                                       b0, (float*)pHp, K0P, 0, 0);

    // layer 1 (fused assemble): -> bufA
    gemm_l1<<<dim3(SN / 128, 2), 256, SMEM_L1>>>(hr, W0, (const float*)pWt1, b1, (float*)pA);

    // layer 2: bufA -> bufB
    gemm_tf32<<<dim3(SN / 128, 2), 256, SMEM_GEMM>>>((const float*)pA, (const float*)pWt2,
                                                     b2, (float*)pB, 256, 1, 1);

    // layer 3 + final layer fused: bufB -> g_pred (atomics)
    gemm_l3<<<dim3(SN / 128, 2), 256, SMEM_L3>>>((const float*)pB, (const float*)pWt3,
                                                 b3, W4);

    ensemble<<<QN / 256, 256>>>(hr, b4, out);
}